// round 10
// baseline (speedup 1.0000x reference)
#include <cuda_runtime.h>

#define LL    128
#define NANG  120
#define TB    128
#define TX    16
#define TY    16
#define ZC    16
#define ROWS  32
#define RS    48     // floats; rows r,r+1 bank-disjoint -> conflict-free STS.128

typedef unsigned long long u64t;

__device__ __forceinline__ u64t pack2(float x, float y) {
    u64t r;
    asm("mov.b64 %0, {%1, %2};" : "=l"(r) : "f"(x), "f"(y));
    return r;
}
__device__ __forceinline__ void ffma2(u64t &acc, u64t v, u64t w) {
    asm("fma.rn.f32x2 %0, %1, %2, %0;" : "+l"(acc) : "l"(v), "l"(w));
}
__device__ __forceinline__ void unpack2(u64t v, float &x, float &y) {
    asm("mov.b64 {%0, %1}, %2;" : "=f"(x), "=f"(y) : "l"(v));
}
__device__ __forceinline__ void lds2(u64t &a, u64t &b, unsigned addr) {
    asm volatile("ld.shared.v2.u64 {%0, %1}, [%2];" : "=l"(a), "=l"(b) : "r"(addr));
}

// validity-weighted tap sum along one axis (replaces bounds predicates)
__device__ __forceinline__ float gfun(float t) {
    return fmaxf(0.0f, fminf(fminf(t + 1.0f, 128.0f - t), 1.0f));
}

// pixel P uses window rows 0,1; pixel Q uses rows 0,1,2 (row 2 only when dd)
__device__ __forceinline__ void inner3(unsigned addr, bool dd,
                                       u64t Wp0, u64t Wp1,
                                       u64t Wq0, u64t Wq1, u64t Wq2,
                                       u64t *accP, u64t *accQ) {
    #pragma unroll
    for (int q = 0; q < 4; ++q) {
        u64t p00, p01, p10, p11;
        u64t p20 = 0ULL, p21 = 0ULL;          // safe when Wq2==0 (skip load)
        lds2(p00, p01, addr + q * 16);
        lds2(p10, p11, addr + RS * 4 + q * 16);
        if (dd) lds2(p20, p21, addr + 2 * RS * 4 + q * 16);
        ffma2(accP[2 * q],     p00, Wp0);
        ffma2(accP[2 * q + 1], p01, Wp0);
        ffma2(accP[2 * q],     p10, Wp1);
        ffma2(accP[2 * q + 1], p11, Wp1);
        ffma2(accQ[2 * q],     p00, Wq0);
        ffma2(accQ[2 * q + 1], p01, Wq0);
        ffma2(accQ[2 * q],     p10, Wq1);
        ffma2(accQ[2 * q + 1], p11, Wq1);
        ffma2(accQ[2 * q],     p20, Wq2);
        ffma2(accQ[2 * q + 1], p21, Wq2);
    }
}

__global__ __launch_bounds__(TB, 7)
void bp_kernel(const float * __restrict__ image, const float * __restrict__ angles,
               float * __restrict__ out) {
    __shared__ float4 s_tab[NANG];     // (cos, sin, unused, ymin bits)
    __shared__ __align__(16) float s_img[2][ROWS * RS];

    const int tid = threadIdx.x;
    const int tileX0 = (blockIdx.x & 7) * TX;
    const int tileY0 = (blockIdx.x >> 3) * TY;
    const float X0f = tileX0 - 63.5f, X1f = X0f + (TX - 1);
    const float Y0f = tileY0 - 63.5f, Y1f = Y0f + (TY - 1);

    if (tid < NANG) {
        float ph = -angles[tid] * 0.017453292519943295f;
        float sv, cv;
        sincosf(ph, &sv, &cv);
        float m = fminf(-sv * X0f, -sv * X1f) + fminf(cv * Y0f, cv * Y1f) + 63.5f;
        int ym = (int)floorf(m) - 1;
        s_tab[tid] = make_float4(cv, sv, 0.0f, __int_as_float(ym));
    }

    const int z0 = blockIdx.y * ZC;
    const int b  = blockIdx.z;

    const int warp = tid >> 5, lane = tid & 31;
    const int px = tileX0 + (warp & 1) * 8 + (lane & 7);
    const int pr = (warp >> 1) * 4 + (lane >> 3);
    const int py = tileY0 + 2 * pr;
    const float Xp = px - 63.5f, Yp = py - 63.5f;

    const float *img_b = image + (size_t)b * NANG * LL * LL + z0;

    // staging mapping: one float4 per thread per angle
    const int zq   = tid & 3;          // 16B quad within the 16-float row
    const int srow = tid >> 2;         // staged row 0..31
    const unsigned sts_off = (unsigned)(srow * RS * 4 + zq * 16);

    u64t acc[16];    // [0..7]=pixel1(py), [8..15]=pixel2(py+1)
    #pragma unroll
    for (int i = 0; i < 16; ++i) acc[i] = 0ULL;
    float n1 = 0.0f, n2 = 0.0f;

    __syncthreads();  // s_tab ready

    const unsigned sm0 = (unsigned)__cvta_generic_to_shared(&s_img[0][0]);

    // prologue: stage angle 0; LDG angle 1 into hold
    {
        int gy = __float_as_int(s_tab[0].w) + srow;
        float4 t = make_float4(0.f, 0.f, 0.f, 0.f);
        if ((unsigned)gy < (unsigned)LL)
            t = __ldg(reinterpret_cast<const float4 *>(img_b + gy * LL) + zq);
        *reinterpret_cast<float4 *>(reinterpret_cast<char *>(&s_img[0][0]) + sts_off) = t;
    }
    float4 hold = make_float4(0.f, 0.f, 0.f, 0.f);
    {
        int gy = __float_as_int(s_tab[1].w) + srow;
        if ((unsigned)gy < (unsigned)LL)
            hold = __ldg(reinterpret_cast<const float4 *>(img_b + LL * LL + gy * LL) + zq);
    }

    for (int a = 0; a < NANG; ++a) {
        __syncthreads();   // buf[a&1] staged (STS drained); readers of buf[(a+1)&1] done

        const float4 tb = s_tab[a];
        const float c = tb.x, s = tb.y;
        const int   ya = __float_as_int(tb.w);

        float sx = fmaf(c, Xp, fmaf(s, Yp, 63.5f));
        float sy = fmaf(c, Yp, fmaf(-s, Xp, 63.5f));
        float sx2 = sx + s;
        float sy2 = sy + c;
        float y0f = floorf(sy), y2f = floorf(sy2);
        float wy  = sy  - y0f;
        float wy2 = sy2 - y2f;

        float hx  = gfun(sx);
        float hx2 = gfun(sx2);
        n1 = fmaf(hx,  gfun(sy),  n1);
        n2 = fmaf(hx2, gfun(sy2), n2);

        float A1 = hx  * wy,  A0 = hx  - A1;   // taps rows y0, y0+1 (OOB rows = 0)
        float B1 = hx2 * wy2, B0 = hx2 - B1;

        const unsigned smb = sm0 + (unsigned)((a & 1) * (ROWS * RS * 4));

        if (c >= 0.0f) {
            // y2f >= y0f: pixel1 at window rows 0,1; pixel2 shifted by dd
            bool dd = (y2f > y0f);
            int r0 = (int)y0f - ya;                 // in [0, ROWS-3]
            float q0 = dd ? 0.0f : B0;
            float q1 = dd ? B0   : B1;
            float q2 = dd ? B1   : 0.0f;
            inner3(smb + (unsigned)r0 * (RS * 4), dd,
                   pack2(A0, A0), pack2(A1, A1),
                   pack2(q0, q0), pack2(q1, q1), pack2(q2, q2),
                   acc, acc + 8);
        } else {
            // y2f <= y0f: pixel2 at window rows 0,1; pixel1 shifted by dd
            bool dd = (y2f < y0f);
            int r0 = (int)y2f - ya;
            float q0 = dd ? 0.0f : A0;
            float q1 = dd ? A0   : A1;
            float q2 = dd ? A1   : 0.0f;
            inner3(smb + (unsigned)r0 * (RS * 4), dd,
                   pack2(B0, B0), pack2(B1, B1),
                   pack2(q0, q0), pack2(q1, q1), pack2(q2, q2),
                   acc + 8, acc);
        }

        // stage next: STS(a+1) from hold (LDG'd one full body ago), then LDG(a+2)
        if (a + 1 < NANG) {
            *reinterpret_cast<float4 *>(
                reinterpret_cast<char *>(&s_img[(a + 1) & 1][0]) + sts_off) = hold;
        }
        if (a + 2 < NANG) {
            int gy = __float_as_int(s_tab[a + 2].w) + srow;
            hold = make_float4(0.f, 0.f, 0.f, 0.f);
            if ((unsigned)gy < (unsigned)LL)
                hold = __ldg(reinterpret_cast<const float4 *>(
                                 img_b + (size_t)(a + 2) * LL * LL + gy * LL) + zq);
        }
    }

    // epilogue: out = obj / (norm + delta)
    float inv1 = 1.0f / (n1 + 1e-11f);
    float inv2 = 1.0f / (n2 + 1e-11f);
    float *op = out + (((size_t)b * LL + px) * LL + py) * LL + z0;
    #pragma unroll
    for (int q = 0; q < 4; ++q) {
        float ax, ay, bx, by;
        unpack2(acc[2 * q],     ax, ay);
        unpack2(acc[2 * q + 1], bx, by);
        *reinterpret_cast<float4 *>(op + q * 4) =
            make_float4(ax * inv1, ay * inv1, bx * inv1, by * inv1);
    }
    float *op2 = op + LL;
    #pragma unroll
    for (int q = 0; q < 4; ++q) {
        float ax, ay, bx, by;
        unpack2(acc[8 + 2 * q],     ax, ay);
        unpack2(acc[8 + 2 * q + 1], bx, by);
        *reinterpret_cast<float4 *>(op2 + q * 4) =
            make_float4(ax * inv2, ay * inv2, bx * inv2, by * inv2);
    }
}

extern "C" void kernel_launch(void *const *d_in, const int *in_sizes, int n_in,
                              void *d_out, int out_size) {
    const float *image  = (const float *)d_in[0];
    const float *angles = (const float *)d_in[1];
    float *out = (float *)d_out;
    dim3 grid(64, LL / ZC /*8*/, 2 /*B*/);
    bp_kernel<<<grid, TB>>>(image, angles, out);
}

// round 11
// speedup vs baseline: 2.0057x; 2.0057x over previous
#include <cuda_runtime.h>

#define LL    128
#define NANG  120
#define TB    128
#define TX    16
#define TY    16
#define ZC    16
#define ROWS  32
#define RS    20     // 20 mod 32 = 20: rows k apart collide only at k=8 (outside span)

typedef unsigned long long u64t;

__device__ __forceinline__ u64t pack2(float x, float y) {
    u64t r;
    asm("mov.b64 %0, {%1, %2};" : "=l"(r) : "f"(x), "f"(y));
    return r;
}
__device__ __forceinline__ void ffma2(u64t &acc, u64t v, u64t w) {
    asm("fma.rn.f32x2 %0, %1, %2, %0;" : "+l"(acc) : "l"(v), "l"(w));
}
__device__ __forceinline__ void unpack2(u64t v, float &x, float &y) {
    asm("mov.b64 {%0, %1}, %2;" : "=f"(x), "=f"(y) : "l"(v));
}
__device__ __forceinline__ void lds2(u64t &a, u64t &b, unsigned addr) {
    asm volatile("ld.shared.v2.u64 {%0, %1}, [%2];" : "=l"(a), "=l"(b) : "r"(addr));
}
// predicated variant: loads only when pred!=0, else returns zeros (no branch)
__device__ __forceinline__ void lds2p(u64t &a, u64t &b, unsigned addr, unsigned pred) {
    asm volatile(
        "{\n\t.reg .pred p;\n\t"
        "setp.ne.u32 p, %3, 0;\n\t"
        "mov.u64 %0, 0;\n\t"
        "mov.u64 %1, 0;\n\t"
        "@p ld.shared.v2.u64 {%0, %1}, [%2];\n\t}"
        : "=l"(a), "=l"(b) : "r"(addr), "r"(pred));
}

// validity-weighted tap sum along one axis (replaces bounds predicates)
__device__ __forceinline__ float gfun(float t) {
    return fmaxf(0.0f, fminf(fminf(t + 1.0f, 128.0f - t), 1.0f));
}

// pixel P uses window rows 0,1; pixel Q rows 0,1,2 (row 2 loaded only when dd)
__device__ __forceinline__ void inner3(unsigned addr, unsigned dd,
                                       u64t Wp0, u64t Wp1,
                                       u64t Wq0, u64t Wq1, u64t Wq2,
                                       u64t *accP, u64t *accQ) {
    #pragma unroll
    for (int q = 0; q < 4; ++q) {
        u64t p00, p01, p10, p11, p20, p21;
        lds2(p00, p01, addr + q * 16);
        lds2(p10, p11, addr + RS * 4 + q * 16);
        lds2p(p20, p21, addr + 2 * RS * 4 + q * 16, dd);
        ffma2(accP[2 * q],     p00, Wp0);
        ffma2(accP[2 * q + 1], p01, Wp0);
        ffma2(accP[2 * q],     p10, Wp1);
        ffma2(accP[2 * q + 1], p11, Wp1);
        ffma2(accQ[2 * q],     p00, Wq0);
        ffma2(accQ[2 * q + 1], p01, Wq0);
        ffma2(accQ[2 * q],     p10, Wq1);
        ffma2(accQ[2 * q + 1], p11, Wq1);
        ffma2(accQ[2 * q],     p20, Wq2);
        ffma2(accQ[2 * q + 1], p21, Wq2);
    }
}

__global__ __launch_bounds__(TB, 7)
void bp_kernel(const float * __restrict__ image, const float * __restrict__ angles,
               float * __restrict__ out) {
    __shared__ float4 s_tab[NANG];     // (cos, sin, unused, ymin bits)
    __shared__ __align__(16) float s_img[2][ROWS * RS];

    const int tid = threadIdx.x;
    const int tileX0 = (blockIdx.x & 7) * TX;
    const int tileY0 = (blockIdx.x >> 3) * TY;
    const float X0f = tileX0 - 63.5f, X1f = X0f + (TX - 1);
    const float Y0f = tileY0 - 63.5f, Y1f = Y0f + (TY - 1);

    if (tid < NANG) {
        float ph = -angles[tid] * 0.017453292519943295f;
        float sv, cv;
        sincosf(ph, &sv, &cv);
        float m = fminf(-sv * X0f, -sv * X1f) + fminf(cv * Y0f, cv * Y1f) + 63.5f;
        int ym = (int)floorf(m) - 1;
        s_tab[tid] = make_float4(cv, sv, 0.0f, __int_as_float(ym));
    }

    const int z0 = blockIdx.y * ZC;
    const int b  = blockIdx.z;

    const int warp = tid >> 5, lane = tid & 31;
    const int px = tileX0 + (warp & 1) * 8 + (lane & 7);
    const int pr = (warp >> 1) * 4 + (lane >> 3);
    const int py = tileY0 + 2 * pr;
    const float Xp = px - 63.5f, Yp = py - 63.5f;

    const float *img_b = image + (size_t)b * NANG * LL * LL + z0;

    // staging: one float4 per thread per angle; srow = tid>>2 covers rows 0..31,
    // zq = tid&3 covers the 16-float row. RS=20 -> STS.128 conflict-free (4/bank).
    const int zq   = tid & 3;
    const int srow = tid >> 2;
    const unsigned sts_off = (unsigned)(srow * RS * 4 + zq * 16);

    u64t acc[16];    // [0..7]=pixel1(py), [8..15]=pixel2(py+1)
    #pragma unroll
    for (int i = 0; i < 16; ++i) acc[i] = 0ULL;
    float n1 = 0.0f, n2 = 0.0f;

    __syncthreads();  // s_tab ready

    const unsigned sm0 = (unsigned)__cvta_generic_to_shared(&s_img[0][0]);

    // prologue: stage angle 0; LDG angle 1 into hold
    {
        int gy = __float_as_int(s_tab[0].w) + srow;
        float4 t = make_float4(0.f, 0.f, 0.f, 0.f);
        if ((unsigned)gy < (unsigned)LL)
            t = __ldg(reinterpret_cast<const float4 *>(img_b + gy * LL) + zq);
        *reinterpret_cast<float4 *>(reinterpret_cast<char *>(&s_img[0][0]) + sts_off) = t;
    }
    float4 hold = make_float4(0.f, 0.f, 0.f, 0.f);
    {
        int gy = __float_as_int(s_tab[1].w) + srow;
        if ((unsigned)gy < (unsigned)LL)
            hold = __ldg(reinterpret_cast<const float4 *>(img_b + LL * LL + gy * LL) + zq);
    }

    for (int a = 0; a < NANG; ++a) {
        __syncthreads();   // buf[a&1] staged (STS drained); readers of buf[(a+1)&1] done

        const float4 tb = s_tab[a];
        const float c = tb.x, s = tb.y;
        const int   ya = __float_as_int(tb.w);

        float sx = fmaf(c, Xp, fmaf(s, Yp, 63.5f));
        float sy = fmaf(c, Yp, fmaf(-s, Xp, 63.5f));
        float sx2 = sx + s;
        float sy2 = sy + c;
        float y0f = floorf(sy), y2f = floorf(sy2);
        float wy  = sy  - y0f;
        float wy2 = sy2 - y2f;

        float hx  = gfun(sx);
        float hx2 = gfun(sx2);
        n1 = fmaf(hx,  gfun(sy),  n1);
        n2 = fmaf(hx2, gfun(sy2), n2);

        float A1 = hx  * wy,  A0 = hx  - A1;   // taps rows y0, y0+1 (OOB rows = 0)
        float B1 = hx2 * wy2, B0 = hx2 - B1;

        const unsigned smb = sm0 + (unsigned)((a & 1) * (ROWS * RS * 4));

        if (c >= 0.0f) {
            // y2f >= y0f: pixel1 at window rows 0,1; pixel2 shifted by dd
            unsigned dd = (y2f > y0f) ? 1u : 0u;
            int r0 = (int)y0f - ya;                 // in [0, ROWS-3]
            float q0 = dd ? 0.0f : B0;
            float q1 = dd ? B0   : B1;
            float q2 = dd ? B1   : 0.0f;
            inner3(smb + (unsigned)r0 * (RS * 4), dd,
                   pack2(A0, A0), pack2(A1, A1),
                   pack2(q0, q0), pack2(q1, q1), pack2(q2, q2),
                   acc, acc + 8);
        } else {
            // y2f <= y0f: pixel2 at window rows 0,1; pixel1 shifted by dd
            unsigned dd = (y2f < y0f) ? 1u : 0u;
            int r0 = (int)y2f - ya;
            float q0 = dd ? 0.0f : A0;
            float q1 = dd ? A0   : A1;
            float q2 = dd ? A1   : 0.0f;
            inner3(smb + (unsigned)r0 * (RS * 4), dd,
                   pack2(B0, B0), pack2(B1, B1),
                   pack2(q0, q0), pack2(q1, q1), pack2(q2, q2),
                   acc + 8, acc);
        }

        // stage next: STS(a+1) from hold (LDG'd one full body ago), then LDG(a+2)
        if (a + 1 < NANG) {
            *reinterpret_cast<float4 *>(
                reinterpret_cast<char *>(&s_img[(a + 1) & 1][0]) + sts_off) = hold;
        }
        if (a + 2 < NANG) {
            int gy = __float_as_int(s_tab[a + 2].w) + srow;
            hold = make_float4(0.f, 0.f, 0.f, 0.f);
            if ((unsigned)gy < (unsigned)LL)
                hold = __ldg(reinterpret_cast<const float4 *>(
                                 img_b + (size_t)(a + 2) * LL * LL + gy * LL) + zq);
        }
    }

    // epilogue: out = obj / (norm + delta)
    float inv1 = 1.0f / (n1 + 1e-11f);
    float inv2 = 1.0f / (n2 + 1e-11f);
    float *op = out + (((size_t)b * LL + px) * LL + py) * LL + z0;
    #pragma unroll
    for (int q = 0; q < 4; ++q) {
        float ax, ay, bx, by;
        unpack2(acc[2 * q],     ax, ay);
        unpack2(acc[2 * q + 1], bx, by);
        *reinterpret_cast<float4 *>(op + q * 4) =
            make_float4(ax * inv1, ay * inv1, bx * inv1, by * inv1);
    }
    float *op2 = op + LL;
    #pragma unroll
    for (int q = 0; q < 4; ++q) {
        float ax, ay, bx, by;
        unpack2(acc[8 + 2 * q],     ax, ay);
        unpack2(acc[8 + 2 * q + 1], bx, by);
        *reinterpret_cast<float4 *>(op2 + q * 4) =
            make_float4(ax * inv2, ay * inv2, bx * inv2, by * inv2);
    }
}

extern "C" void kernel_launch(void *const *d_in, const int *in_sizes, int n_in,
                              void *d_out, int out_size) {
    const float *image  = (const float *)d_in[0];
    const float *angles = (const float *)d_in[1];
    float *out = (float *)d_out;
    dim3 grid(64, LL / ZC /*8*/, 2 /*B*/);
    bp_kernel<<<grid, TB>>>(image, angles, out);
}

// round 13
// speedup vs baseline: 2.2188x; 1.1062x over previous
#include <cuda_runtime.h>
#include <cuda_fp16.h>

#define LL    128
#define NANG  120
#define TB    128
#define TX    16
#define TY    16
#define ZC    16
#define ROWS  32
#define RSB   48      // bytes per staged row: 32 B data (16 z fp16) + 16 B pad
#define ABLK  8       // angles per fp16-partial block (15 blocks)

typedef unsigned long long u64t;
typedef unsigned int u32t;

__device__ __forceinline__ u64t pack2(float x, float y) {
    u64t r;
    asm("mov.b64 %0, {%1, %2};" : "=l"(r) : "f"(x), "f"(y));
    return r;
}
__device__ __forceinline__ void unpack2(u64t v, float &x, float &y) {
    asm("mov.b64 {%0, %1}, %2;" : "=f"(x), "=f"(y) : "l"(v));
}
__device__ __forceinline__ void fadd2(u64t &acc, u64t v) {
    asm("add.rn.f32x2 %0, %0, %1;" : "+l"(acc) : "l"(v));
}
// bit-casts between half2 and u32 (no intrinsic dependency)
__device__ __forceinline__ u32t h2_as_u32(__half2 h) {
    return *reinterpret_cast<u32t *>(&h);
}
__device__ __forceinline__ __half2 asH2(u32t v) {
    return *reinterpret_cast<__half2 *>(&v);
}
// 16B shared load = 8 halves (8 z) as 4 half2 words
__device__ __forceinline__ void lds4(u32t h[4], unsigned addr) {
    asm volatile("ld.shared.v4.b32 {%0, %1, %2, %3}, [%4];"
                 : "=r"(h[0]), "=r"(h[1]), "=r"(h[2]), "=r"(h[3]) : "r"(addr));
}
// predicated: zeros when pred==0 (no branch)
__device__ __forceinline__ void lds4p(u32t h[4], unsigned addr, unsigned pred) {
    asm volatile(
        "{\n\t.reg .pred p;\n\t"
        "setp.ne.u32 p, %5, 0;\n\t"
        "mov.b32 %0, 0;\n\tmov.b32 %1, 0;\n\tmov.b32 %2, 0;\n\tmov.b32 %3, 0;\n\t"
        "@p ld.shared.v4.b32 {%0, %1, %2, %3}, [%4];\n\t}"
        : "=r"(h[0]), "=r"(h[1]), "=r"(h[2]), "=r"(h[3]) : "r"(addr), "r"(pred));
}

// validity-weighted tap sum along one axis
__device__ __forceinline__ float gfun(float t) {
    return fmaxf(0.0f, fminf(fminf(t + 1.0f, 128.0f - t), 1.0f));
}

// pixel P: window rows 0,1; pixel Q: rows 0,1,2 (row 2 loaded only when dd)
__device__ __forceinline__ void inner_h(unsigned addr, unsigned dd,
                                        __half2 Wp0, __half2 Wp1,
                                        __half2 Wq0, __half2 Wq1, __half2 Wq2,
                                        __half2 *pP, __half2 *pQ) {
    #pragma unroll
    for (int q = 0; q < 2; ++q) {
        u32t h[4], g[4], e[4];
        lds4(h, addr + q * 16);
        lds4(g, addr + RSB + q * 16);
        lds4p(e, addr + 2 * RSB + q * 16, dd);
        #pragma unroll
        for (int i = 0; i < 4; ++i) {
            int j = q * 4 + i;
            pP[j] = __hfma2(asH2(h[i]), Wp0, pP[j]);
            pP[j] = __hfma2(asH2(g[i]), Wp1, pP[j]);
            pQ[j] = __hfma2(asH2(h[i]), Wq0, pQ[j]);
            pQ[j] = __hfma2(asH2(g[i]), Wq1, pQ[j]);
            pQ[j] = __hfma2(asH2(e[i]), Wq2, pQ[j]);
        }
    }
}

__global__ __launch_bounds__(TB, 7)
void bp_kernel(const float * __restrict__ image, const float * __restrict__ angles,
               float * __restrict__ out) {
    __shared__ float4 s_tab[NANG];     // (cos, sin, unused, ymin bits)
    __shared__ __align__(16) char s_img[2][ROWS * RSB];

    const int tid = threadIdx.x;
    const int tileX0 = (blockIdx.x & 7) * TX;
    const int tileY0 = (blockIdx.x >> 3) * TY;

    {
        const float X0f = tileX0 - 63.5f, X1f = X0f + (TX - 1);
        const float Y0f = tileY0 - 63.5f, Y1f = Y0f + (TY - 1);
        if (tid < NANG) {
            float ph = -angles[tid] * 0.017453292519943295f;
            float sv, cv;
            sincosf(ph, &sv, &cv);
            float m = fminf(-sv * X0f, -sv * X1f) + fminf(cv * Y0f, cv * Y1f) + 63.5f;
            int ym = (int)floorf(m) - 1;
            s_tab[tid] = make_float4(cv, sv, 0.0f, __int_as_float(ym));
        }
    }

    const int z0 = blockIdx.y * ZC;
    const int b  = blockIdx.z;

    const int warp = tid >> 5, lane = tid & 31;
    const int px = tileX0 + (warp & 1) * 8 + (lane & 7);
    const int py = tileY0 + 2 * ((warp >> 1) * 4 + (lane >> 3));
    const float Xp = px - 63.5f, Yp = py - 63.5f;

    const float *img_b = image + (size_t)b * NANG * LL * LL + z0;

    // staging: thread -> (row srow, z-quad zq); converts float4 -> 2 half2 -> STS.64
    const int zq   = tid & 3;
    const int srow = tid >> 2;
    const unsigned sts_off = (unsigned)(srow * RSB + zq * 8);

    u64t acc[16];    // fp32 packed: [0..7]=pixel1(py), [8..15]=pixel2(py+1)
    #pragma unroll
    for (int i = 0; i < 16; ++i) acc[i] = 0ULL;
    float n1 = 0.0f, n2 = 0.0f;

    __syncthreads();  // s_tab ready

    const unsigned sm0 = (unsigned)__cvta_generic_to_shared(&s_img[0][0]);

    // prologue: stage angle 0; LDG+convert angle 1 into hold
    {
        int gy = __float_as_int(s_tab[0].w) + srow;
        uint2 hv = make_uint2(0u, 0u);
        if ((unsigned)gy < (unsigned)LL) {
            float4 t = __ldg(reinterpret_cast<const float4 *>(img_b + gy * LL) + zq);
            hv.x = h2_as_u32(__floats2half2_rn(t.x, t.y));
            hv.y = h2_as_u32(__floats2half2_rn(t.z, t.w));
        }
        *reinterpret_cast<uint2 *>(&s_img[0][0] + sts_off) = hv;
    }
    uint2 hold = make_uint2(0u, 0u);
    {
        int gy = __float_as_int(s_tab[1].w) + srow;
        if ((unsigned)gy < (unsigned)LL) {
            float4 t = __ldg(reinterpret_cast<const float4 *>(img_b + LL * LL + gy * LL) + zq);
            hold.x = h2_as_u32(__floats2half2_rn(t.x, t.y));
            hold.y = h2_as_u32(__floats2half2_rn(t.z, t.w));
        }
    }

    for (int blk = 0; blk < NANG / ABLK; ++blk) {
        __half2 pP[8], pQ[8];        // fp16 partials for this 8-angle block
        #pragma unroll
        for (int i = 0; i < 8; ++i) {
            pP[i] = __floats2half2_rn(0.f, 0.f);
            pQ[i] = __floats2half2_rn(0.f, 0.f);
        }

        for (int k = 0; k < ABLK; ++k) {
            const int a = blk * ABLK + k;
            __syncthreads();   // buf[a&1] staged; readers of buf[(a+1)&1] done

            const float4 tb = s_tab[a];
            const float c = tb.x, s = tb.y;
            const int   ya = __float_as_int(tb.w);

            float sx = fmaf(c, Xp, fmaf(s, Yp, 63.5f));
            float sy = fmaf(c, Yp, fmaf(-s, Xp, 63.5f));
            float sx2 = sx + s;
            float sy2 = sy + c;
            float y0f = floorf(sy), y2f = floorf(sy2);
            float wy  = sy  - y0f;
            float wy2 = sy2 - y2f;

            float hx  = gfun(sx);
            float hx2 = gfun(sx2);
            n1 = fmaf(hx,  gfun(sy),  n1);
            n2 = fmaf(hx2, gfun(sy2), n2);

            float A1 = hx  * wy,  A0 = hx  - A1;   // rows y0, y0+1 (OOB rows = 0)
            float B1 = hx2 * wy2, B0 = hx2 - B1;

            const unsigned smb = sm0 + (unsigned)((a & 1) * (ROWS * RSB));

            if (c >= 0.0f) {
                unsigned dd = (y2f > y0f) ? 1u : 0u;
                int r0 = (int)y0f - ya;                 // in [0, ROWS-3]
                float q0 = dd ? 0.0f : B0;
                float q1 = dd ? B0   : B1;
                float q2 = dd ? B1   : 0.0f;
                inner_h(smb + (unsigned)r0 * RSB, dd,
                        __float2half2_rn(A0), __float2half2_rn(A1),
                        __float2half2_rn(q0), __float2half2_rn(q1), __float2half2_rn(q2),
                        pP, pQ);
            } else {
                unsigned dd = (y2f < y0f) ? 1u : 0u;
                int r0 = (int)y2f - ya;
                float q0 = dd ? 0.0f : A0;
                float q1 = dd ? A0   : A1;
                float q2 = dd ? A1   : 0.0f;
                inner_h(smb + (unsigned)r0 * RSB, dd,
                        __float2half2_rn(B0), __float2half2_rn(B1),
                        __float2half2_rn(q0), __float2half2_rn(q1), __float2half2_rn(q2),
                        pQ, pP);
            }

            // stage next: STS(a+1) from hold (converted one body ago), then LDG(a+2)
            if (a + 1 < NANG) {
                *reinterpret_cast<uint2 *>(&s_img[(a + 1) & 1][0] + sts_off) = hold;
            }
            if (a + 2 < NANG) {
                int gy = __float_as_int(s_tab[a + 2].w) + srow;
                hold = make_uint2(0u, 0u);
                if ((unsigned)gy < (unsigned)LL) {
                    float4 t = __ldg(reinterpret_cast<const float4 *>(
                                         img_b + (size_t)(a + 2) * LL * LL + gy * LL) + zq);
                    hold.x = h2_as_u32(__floats2half2_rn(t.x, t.y));
                    hold.y = h2_as_u32(__floats2half2_rn(t.z, t.w));
                }
            }
        }

        // flush fp16 partials into fp32 packed accumulators
        #pragma unroll
        for (int i = 0; i < 8; ++i) {
            float2 f1 = __half22float2(pP[i]);
            fadd2(acc[i],     pack2(f1.x, f1.y));
            float2 f2 = __half22float2(pQ[i]);
            fadd2(acc[8 + i], pack2(f2.x, f2.y));
        }
    }

    // epilogue: out = obj / (norm + delta)
    float inv1 = 1.0f / (n1 + 1e-11f);
    float inv2 = 1.0f / (n2 + 1e-11f);
    float *op = out + (((size_t)b * LL + px) * LL + py) * LL + z0;
    #pragma unroll
    for (int q = 0; q < 4; ++q) {
        float ax, ay, bx, by;
        unpack2(acc[2 * q],     ax, ay);
        unpack2(acc[2 * q + 1], bx, by);
        *reinterpret_cast<float4 *>(op + q * 4) =
            make_float4(ax * inv1, ay * inv1, bx * inv1, by * inv1);
    }
    float *op2 = op + LL;
    #pragma unroll
    for (int q = 0; q < 4; ++q) {
        float ax, ay, bx, by;
        unpack2(acc[8 + 2 * q],     ax, ay);
        unpack2(acc[8 + 2 * q + 1], bx, by);
        *reinterpret_cast<float4 *>(op2 + q * 4) =
            make_float4(ax * inv2, ay * inv2, bx * inv2, by * inv2);
    }
}

extern "C" void kernel_launch(void *const *d_in, const int *in_sizes, int n_in,
                              void *d_out, int out_size) {
    const float *image  = (const float *)d_in[0];
    const float *angles = (const float *)d_in[1];
    float *out = (float *)d_out;
    dim3 grid(64, LL / ZC /*8*/, 2 /*B*/);
    bp_kernel<<<grid, TB>>>(image, angles, out);
}

// round 14
// speedup vs baseline: 2.4392x; 1.0993x over previous
#include <cuda_runtime.h>
#include <cuda_fp16.h>

#define LL    128
#define NANG  120
#define TB    128
#define TX    16
#define TY    8
#define ZC    32      // z per thread (single pixel per thread)
#define ROWS  32
#define RSB   80      // bytes per staged row: 64 B data (32 z fp16) + 16 B pad
#define PY    192     // padded rows in fp16 scratch
#define YOFF  32      // pad offset: scratch row = image y + YOFF
#define ABLK  8       // angles per fp16-partial block

typedef unsigned long long u64t;
typedef unsigned int u32t;

// padded fp16 image: [b][a][y+YOFF][z], zero outside y in [0,128)
__device__ __half g_pad[2][NANG][PY][LL];

__device__ __forceinline__ u64t pack2(float x, float y) {
    u64t r;
    asm("mov.b64 %0, {%1, %2};" : "=l"(r) : "f"(x), "f"(y));
    return r;
}
__device__ __forceinline__ void unpack2(u64t v, float &x, float &y) {
    asm("mov.b64 {%0, %1}, %2;" : "=f"(x), "=f"(y) : "l"(v));
}
__device__ __forceinline__ void fadd2(u64t &acc, u64t v) {
    asm("add.rn.f32x2 %0, %0, %1;" : "+l"(acc) : "l"(v));
}
__device__ __forceinline__ u32t h2_as_u32(__half2 h) {
    return *reinterpret_cast<u32t *>(&h);
}
__device__ __forceinline__ __half2 asH2(u32t v) {
    return *reinterpret_cast<__half2 *>(&v);
}
__device__ __forceinline__ void lds4(u32t h[4], unsigned addr) {
    asm volatile("ld.shared.v4.b32 {%0, %1, %2, %3}, [%4];"
                 : "=r"(h[0]), "=r"(h[1]), "=r"(h[2]), "=r"(h[3]) : "r"(addr));
}

// validity-weighted tap sum along one axis
__device__ __forceinline__ float gfun(float t) {
    return fmaxf(0.0f, fminf(fminf(t + 1.0f, 128.0f - t), 1.0f));
}

// ---------- prep: fp32 image -> zero-padded fp16 scratch ----------
__global__ void prep_kernel(const float * __restrict__ image) {
    int idx = blockIdx.x * blockDim.x + threadIdx.x;   // one uint2 (4 halves) each
    // total = 2 * NANG * PY * (LL/4)
    int z4 = idx & 31;                 // LL/4 = 32
    int py = (idx >> 5) % PY;
    int a  = (idx >> 5) / PY % NANG;
    int b  = idx / (32 * PY * NANG);
    if (b >= 2) return;
    int y = py - YOFF;
    uint2 hv = make_uint2(0u, 0u);
    if ((unsigned)y < (unsigned)LL) {
        float4 v = __ldg(reinterpret_cast<const float4 *>(
                             image + (((size_t)b * NANG + a) * LL + y) * LL) + z4);
        hv.x = h2_as_u32(__floats2half2_rn(v.x, v.y));
        hv.y = h2_as_u32(__floats2half2_rn(v.z, v.w));
    }
    *reinterpret_cast<uint2 *>(&g_pad[b][a][py][z4 * 4]) = hv;
}

// ---------- main ----------
__global__ __launch_bounds__(TB, 7)
void bp_kernel(const float * __restrict__ angles, float * __restrict__ out) {
    __shared__ float4 s_tab[NANG];     // (cos, sin, 0, padded-ymin bits)
    __shared__ __align__(16) char s_img[2][ROWS * RSB];

    const int tid = threadIdx.x;
    const int tileX0 = (blockIdx.x & 7) * TX;
    const int tileY0 = (blockIdx.x >> 3) * TY;

    {
        const float X0f = tileX0 - 63.5f, X1f = X0f + (TX - 1);
        const float Y0f = tileY0 - 63.5f, Y1f = Y0f + (TY - 1);
        if (tid < NANG) {
            float ph = -angles[tid] * 0.017453292519943295f;
            float sv, cv;
            sincosf(ph, &sv, &cv);
            float m = fminf(-sv * X0f, -sv * X1f) + fminf(cv * Y0f, cv * Y1f) + 63.5f;
            int ym = (int)floorf(m) - 1;               // image-space ymin
            s_tab[tid] = make_float4(cv, sv, 0.0f, __int_as_float(ym));
        }
    }

    const int z0 = blockIdx.y * ZC;
    const int b  = blockIdx.z;

    const int warp = tid >> 5, lane = tid & 31;
    const int px = tileX0 + (warp & 1) * 8 + (lane & 7);
    const int py = tileY0 + (warp >> 1) * 4 + (lane >> 3);
    const float Xp = px - 63.5f, Yp = py - 63.5f;

    // staging: thread -> (srow = tid>>2 in 0..31, zq = tid&3); 16B per thread
    const int zq   = tid & 3;
    const int srow = tid >> 2;
    const unsigned sts_off = (unsigned)(srow * RSB + zq * 16);
    const __half *padb = &g_pad[b][0][0][0];

    u64t acc[16];                      // fp32 packed, 32 z
    #pragma unroll
    for (int i = 0; i < 16; ++i) acc[i] = 0ULL;
    float n1 = 0.0f;

    __syncthreads();  // s_tab ready

    const unsigned sm0 = (unsigned)__cvta_generic_to_shared(&s_img[0][0]);

    // prologue: stage angle 0; LDG angle 1 into hold
    {
        int yr = __float_as_int(s_tab[0].w) + YOFF + srow;
        uint4 t = __ldg(reinterpret_cast<const uint4 *>(
                            padb + ((size_t)0 * PY + yr) * LL + z0 + zq * 8));
        *reinterpret_cast<uint4 *>(&s_img[0][0] + sts_off) = t;
    }
    uint4 hold;
    {
        int yr = __float_as_int(s_tab[1].w) + YOFF + srow;
        hold = __ldg(reinterpret_cast<const uint4 *>(
                         padb + ((size_t)1 * PY + yr) * LL + z0 + zq * 8));
    }

    for (int blk = 0; blk < NANG / ABLK; ++blk) {
        __half2 pP[16];                // fp16 partials, 32 z
        #pragma unroll
        for (int i = 0; i < 16; ++i) pP[i] = __floats2half2_rn(0.f, 0.f);

        for (int k = 0; k < ABLK; ++k) {
            const int a = blk * ABLK + k;
            __syncthreads();   // buf[a&1] staged; readers of buf[(a+1)&1] done

            const float4 tb = s_tab[a];
            const float c = tb.x, s = tb.y;
            const int   ya = __float_as_int(tb.w);

            float sx = fmaf(c, Xp, fmaf(s, Yp, 63.5f));
            float sy = fmaf(c, Yp, fmaf(-s, Xp, 63.5f));
            float y0f = floorf(sy);
            float wy  = sy - y0f;

            float hx = gfun(sx);
            n1 = fmaf(hx, gfun(sy), n1);

            float A1 = hx * wy, A0 = hx - A1;    // rows y0, y0+1 (OOB rows = 0)
            __half2 W0 = __float2half2_rn(A0), W1 = __float2half2_rn(A1);

            int r0 = (int)y0f - ya;              // in [1, ROWS-2]
            unsigned addr = sm0 + (unsigned)((a & 1) * (ROWS * RSB))
                                + (unsigned)r0 * RSB;

            #pragma unroll
            for (int q = 0; q < 4; ++q) {
                u32t h[4], g[4];
                lds4(h, addr + q * 16);
                lds4(g, addr + RSB + q * 16);
                #pragma unroll
                for (int i = 0; i < 4; ++i) {
                    int j = q * 4 + i;
                    pP[j] = __hfma2(asH2(h[i]), W0, pP[j]);
                    pP[j] = __hfma2(asH2(g[i]), W1, pP[j]);
                }
            }

            // stage next: STS(a+1) from hold (LDG'd one body ago), then LDG(a+2)
            if (a + 1 < NANG) {
                *reinterpret_cast<uint4 *>(&s_img[(a + 1) & 1][0] + sts_off) = hold;
            }
            if (a + 2 < NANG) {
                int yr = __float_as_int(s_tab[a + 2].w) + YOFF + srow;
                hold = __ldg(reinterpret_cast<const uint4 *>(
                                 padb + ((size_t)(a + 2) * PY + yr) * LL + z0 + zq * 8));
            }
        }

        // flush fp16 partials into fp32 packed accumulators
        #pragma unroll
        for (int i = 0; i < 16; ++i) {
            float2 f = __half22float2(pP[i]);
            fadd2(acc[i], pack2(f.x, f.y));
        }
    }

    // epilogue: out = obj / (norm + delta)
    float inv1 = 1.0f / (n1 + 1e-11f);
    float *op = out + (((size_t)b * LL + px) * LL + py) * LL + z0;
    #pragma unroll
    for (int q = 0; q < 8; ++q) {
        float ax, ay, bx, by;
        unpack2(acc[2 * q],     ax, ay);
        unpack2(acc[2 * q + 1], bx, by);
        *reinterpret_cast<float4 *>(op + q * 4) =
            make_float4(ax * inv1, ay * inv1, bx * inv1, by * inv1);
    }
}

extern "C" void kernel_launch(void *const *d_in, const int *in_sizes, int n_in,
                              void *d_out, int out_size) {
    const float *image  = (const float *)d_in[0];
    const float *angles = (const float *)d_in[1];
    float *out = (float *)d_out;

    int total = 2 * NANG * PY * (LL / 4);
    prep_kernel<<<(total + 255) / 256, 256>>>(image);

    dim3 grid(128 /* 8 x-tiles * 16 y-tiles */, LL / ZC /*4*/, 2 /*B*/);
    bp_kernel<<<grid, TB>>>(angles, out);
}